// round 16
// baseline (speedup 1.0000x reference)
#include <cuda_runtime.h>
#include <math.h>
#include <stdint.h>

// ---------------------------------------------------------------------------
// GraphProjection: 80000 points, 3 cameras, feature pyramid (64/128/256/512 ch)
// out[p] = [coord(3) | max over views(960) | mean(960) | std(960)] -> 2883 f32
// Round 16: SINGLE fused kernel. Each block computes camera matrices once
//   (thread 0, same fp32 op order + DP cofactor inverse as before, in smem);
//   each warp's lanes 0..11 compute their point's 12 gather offsets directly
//   into the register the rolling-window loop shuffles from. Removes the
//   proj launch (~11us) and the g_off global round trip entirely.
//   Gather body = R14/R15 rolling shifted window (all LD/ST 128B aligned).
// ---------------------------------------------------------------------------

#define OUT_STRIDE 2883

struct CamData {
    float B0[9];     // inv(c0^T)
    float c[3][9];   // per-view rotation rows (X,Y,Z normalized)
    float o[3][3];   // per-view camera origin (unnormalized Z)
};

// --- camera matrix, mirroring jnp fp32 op order -----------------------------
__device__ __forceinline__ void cam_mat(const float* prm, float* Crow, float* O) {
    const float PI = 3.14159265358979323846f;
    float theta = prm[0] * PI / 180.0f;
    float e     = prm[1] * PI / 180.0f;
    float camy  = prm[3] * sinf(e);
    float lens  = prm[3] * cosf(e);
    float camx  = lens * cosf(theta);
    float camz  = lens * sinf(theta);

    float Zv[3] = { camx, camy, camz };
    float Yv[3] = { camy * cosf(theta + PI), lens, camy * sinf(theta + PI) };
    float Xv[3] = { Yv[1]*Zv[2] - Yv[2]*Zv[1],
                    Yv[2]*Zv[0] - Yv[0]*Zv[2],
                    Yv[0]*Zv[1] - Yv[1]*Zv[0] };

    float nx = sqrtf(Xv[0]*Xv[0] + Xv[1]*Xv[1] + Xv[2]*Xv[2]);
    float ny = sqrtf(Yv[0]*Yv[0] + Yv[1]*Yv[1] + Yv[2]*Yv[2]);
    float nz = sqrtf(Zv[0]*Zv[0] + Zv[1]*Zv[1] + Zv[2]*Zv[2]);
    for (int k = 0; k < 3; k++) {
        Crow[0*3 + k] = __fdiv_rn(Xv[k], nx);
        Crow[1*3 + k] = __fdiv_rn(Yv[k], ny);
        Crow[2*3 + k] = __fdiv_rn(Zv[k], nz);
        O[k] = Zv[k];
    }
}

__device__ __forceinline__ void cam_setup(const float* __restrict__ cams,
                                          CamData& cam) {
    for (int i = 0; i < 3; i++)
        cam_mat(cams + i * 5, cam.c[i], cam.o[i]);

    // B0 = inv(c0^T), double-precision cofactors of the fp32 matrix.
    double M[3][3];
    for (int r = 0; r < 3; r++)
        for (int k = 0; k < 3; k++)
            M[r][k] = (double)cam.c[0][k*3 + r];

    double det = M[0][0]*(M[1][1]*M[2][2] - M[1][2]*M[2][1])
               - M[0][1]*(M[1][0]*M[2][2] - M[1][2]*M[2][0])
               + M[0][2]*(M[1][0]*M[2][1] - M[1][1]*M[2][0]);
    double inv[3][3];
    inv[0][0] =  (M[1][1]*M[2][2] - M[1][2]*M[2][1]) / det;
    inv[0][1] =  (M[0][2]*M[2][1] - M[0][1]*M[2][2]) / det;
    inv[0][2] =  (M[0][1]*M[1][2] - M[0][2]*M[1][1]) / det;
    inv[1][0] =  (M[1][2]*M[2][0] - M[1][0]*M[2][2]) / det;
    inv[1][1] =  (M[0][0]*M[2][2] - M[0][2]*M[2][0]) / det;
    inv[1][2] =  (M[0][2]*M[1][0] - M[0][0]*M[1][2]) / det;
    inv[2][0] =  (M[1][0]*M[2][1] - M[1][1]*M[2][0]) / det;
    inv[2][1] =  (M[0][1]*M[2][0] - M[0][0]*M[2][1]) / det;
    inv[2][2] =  (M[0][0]*M[1][1] - M[0][1]*M[1][0]) / det;
    for (int k = 0; k < 3; k++)
        for (int j = 0; j < 3; j++)
            cam.B0[k*3 + j] = (float)inv[k][j];
}

// per-lane offset: lane L = view*4 + scale computes its gather base offset
__device__ __forceinline__ int lane_offset(const CamData& cam,
                                           const float* __restrict__ coord,
                                           unsigned p, int L) {
    int i = L >> 2;          // view
    int s = L & 3;           // scale

    float x = __ldg(coord + p*3u + 0u);
    float y = __ldg(coord + p*3u + 1u);
    float z = __ldg(coord + p*3u + 2u);

    float po[3];
    #pragma unroll
    for (int j = 0; j < 3; j++)
        po[j] = x * cam.B0[0*3 + j] + y * cam.B0[1*3 + j]
              + z * cam.B0[2*3 + j] + cam.o[0][j];

    float vx = po[0] - cam.o[i][0];
    float vy = po[1] - cam.o[i][1];
    float vz = po[2] - cam.o[i][2];
    const float* C = cam.c[i];
    float X  = vx*C[0] + vy*C[1] + vz*C[2];
    float Y  = vx*C[3] + vy*C[4] + vz*C[5];
    float Zc = vx*C[6] + vy*C[7] + vz*C[8];

    float negz = -Zc;
    float h = __fdiv_rn(248.0f * (-Y), negz) + 112.0f;
    float w = __fdiv_rn(248.0f * X,    negz) + 112.0f;
    h = fminf(fmaxf(h, 0.0f), 223.0f);
    w = fminf(fmaxf(w, 0.0f), 223.0f);

    // qi = d/224 exact power of two; ds = 56>>s; Cs = 64<<s
    float qi = 0.25f / (float)(1 << s);
    int   ds = 56 >> s;
    int   Cs = 64 << s;
    int ih = (int)(h * qi);
    int iw = (int)(w * qi);
    return (ih * ds + iw) * Cs;
}

// --- fused kernel: per-block cam setup + warp-per-point rolling window ------
__global__ __launch_bounds__(256)
void fused_kernel(const float* __restrict__ f1, const float* __restrict__ f2,
                  const float* __restrict__ f3, const float* __restrict__ f4,
                  const float* __restrict__ coord, const float* __restrict__ cams,
                  float* __restrict__ out) {
    int wid  = threadIdx.x >> 5;
    int lane = threadIdx.x & 31;

    __shared__ CamData cam;
    if (threadIdx.x == 0) cam_setup(cams, cam);
    __syncthreads();

    unsigned p = blockIdx.x * 8u + (unsigned)wid;
    unsigned g = p * (unsigned)OUT_STRIDE;              // < 2^31
    int u = (int)((32u - ((g + 3u) & 31u)) & 31u);      // g+3+u ≡ 0 (mod 32)

    // lanes 0..11 compute this point's 12 offsets (lane = view*4 + scale)
    int v = (lane < 12) ? lane_offset(cam, coord, p, lane) : 0;

    if (lane < 3) out[g + (unsigned)lane] = __ldg(coord + p * 3u + (unsigned)lane);

    int src = (lane + u) & 31;          // shuffle source for window rebuild
    bool send_prev = (lane >= u);       // lane publishes prev (else cur)

    float pm, pn, ps;                   // previous row's stats
    unsigned A;                         // running store index (window base)

    // ---- peeled row 0 (scale 0): compute stats, store head [0,u) ----
    {
        int o0 = __shfl_sync(0xFFFFFFFFu, v, 0);
        int o1 = __shfl_sync(0xFFFFFFFFu, v, 4);
        int o2 = __shfl_sync(0xFFFFFFFFu, v, 8);
        float a = __ldg(f1 + o0 + lane);
        float b = __ldg(f1 + o1 + lane);
        float d = __ldg(f1 + o2 + lane);
        pm = fmaxf(a, fmaxf(b, d));
        pn = (a + b + d) * (1.0f / 3.0f);
        float da = a - pn, db = b - pn, dc = d - pn;
        ps = sqrtf((da*da + db*db + dc*dc) * (1.0f / 3.0f));
        if (lane < u) {
            out[g + 3u + (unsigned)lane]    = pm;
            out[g + 963u + (unsigned)lane]  = pn;
            out[g + 1923u + (unsigned)lane] = ps;
        }
        A = g + 3u + (unsigned)(u + lane);
    }

    // ---- generic segment: CNT rows of scale S, local channels from CL0 ----
#define SEGMENT(F, S, CL0, CNT, UNR)                                           \
    {                                                                          \
        int o0 = __shfl_sync(0xFFFFFFFFu, v, (S));                             \
        int o1 = __shfl_sync(0xFFFFFFFFu, v, 4 + (S));                         \
        int o2 = __shfl_sync(0xFFFFFFFFu, v, 8 + (S));                         \
        int cl = (CL0) + lane;                                                 \
        _Pragma(UNR)                                                           \
        for (int kk = 0; kk < (CNT); kk++) {                                   \
            float a = __ldg((F) + o0 + cl);                                    \
            float b = __ldg((F) + o1 + cl);                                    \
            float d = __ldg((F) + o2 + cl);                                    \
            float cm = fmaxf(a, fmaxf(b, d));                                  \
            float cn = (a + b + d) * (1.0f / 3.0f);                            \
            float da = a - cn, db = b - cn, dc = d - cn;                       \
            float cs = sqrtf((da*da + db*db + dc*dc) * (1.0f / 3.0f));         \
            float wm = __shfl_sync(0xFFFFFFFFu, send_prev ? pm : cm, src);     \
            float wn = __shfl_sync(0xFFFFFFFFu, send_prev ? pn : cn, src);     \
            float ws = __shfl_sync(0xFFFFFFFFu, send_prev ? ps : cs, src);     \
            out[A]         = wm;                                               \
            out[A + 960u]  = wn;                                               \
            out[A + 1920u] = ws;                                               \
            pm = cm; pn = cn; ps = cs; cl += 32; A += 32u;                     \
        }                                                                      \
    }

    SEGMENT(f1, 0, 32,  1, "unroll")       // row 1 (scale 0 done)
    SEGMENT(f2, 1,  0,  4, "unroll 4")     // rows 2..5
    SEGMENT(f3, 2,  0,  8, "unroll 4")     // rows 6..13
    SEGMENT(f4, 3,  0, 16, "unroll 4")     // rows 14..29
#undef SEGMENT

    // ---- tail: window 29 = channels [u+928, 960), from prev only ----
    {
        float wm = __shfl_sync(0xFFFFFFFFu, pm, src);
        float wn = __shfl_sync(0xFFFFFFFFu, pn, src);
        float ws = __shfl_sync(0xFFFFFFFFu, ps, src);
        if (lane < 32 - u) {
            out[A]         = wm;
            out[A + 960u]  = wn;
            out[A + 1920u] = ws;
        }
    }
}

extern "C" void kernel_launch(void* const* d_in, const int* in_sizes, int n_in,
                              void* d_out, int out_size) {
    const float* coord = (const float*)d_in[0];
    const float* cams  = (const float*)d_in[1];
    const float* f1    = (const float*)d_in[2];
    const float* f2    = (const float*)d_in[3];
    const float* f3    = (const float*)d_in[4];
    const float* f4    = (const float*)d_in[5];
    float* out = (float*)d_out;

    int N = in_sizes[0] / 3;

    fused_kernel<<<N / 8, 256>>>(f1, f2, f3, f4, coord, cams, out);
}

// round 17
// speedup vs baseline: 1.5499x; 1.5499x over previous
#include <cuda_runtime.h>
#include <math.h>
#include <stdint.h>

// ---------------------------------------------------------------------------
// GraphProjection: 80000 points, 3 cameras, feature pyramid (64/128/256/512 ch)
// out[p] = [coord(3) | max over views(960) | mean(960) | std(960)] -> 2883 f32
// Round 17: R14 two-kernel structure (best: 170.0us) with the proj kernel's
//   camera setup PARALLELIZED BITWISE-IDENTICALLY: cam_mat per view on its own
//   thread, each DP-cofactor inverse entry on its own thread (det recomputed
//   redundantly -> identical fp64 sequences -> identical B0). 1024-thread proj
//   blocks (79 blocks, one wave). Gather kernel = R14 verbatim.
// ---------------------------------------------------------------------------

#define MAX_N 80000
#define OUT_STRIDE 2883

__device__ int g_off[MAX_N * 12];   // [point][view*4 + scale] flat float offset

struct CamData {
    float B0[9];     // inv(c0^T)
    float c[3][9];   // per-view rotation rows (X,Y,Z normalized)
    float o[3][3];   // per-view camera origin (unnormalized Z)
};

// --- camera matrix, mirroring jnp fp32 op order -----------------------------
__device__ __forceinline__ void cam_mat(const float* prm, float* Crow, float* O) {
    const float PI = 3.14159265358979323846f;
    float theta = prm[0] * PI / 180.0f;
    float e     = prm[1] * PI / 180.0f;
    float camy  = prm[3] * sinf(e);
    float lens  = prm[3] * cosf(e);
    float camx  = lens * cosf(theta);
    float camz  = lens * sinf(theta);

    float Zv[3] = { camx, camy, camz };
    float Yv[3] = { camy * cosf(theta + PI), lens, camy * sinf(theta + PI) };
    float Xv[3] = { Yv[1]*Zv[2] - Yv[2]*Zv[1],
                    Yv[2]*Zv[0] - Yv[0]*Zv[2],
                    Yv[0]*Zv[1] - Yv[1]*Zv[0] };

    float nx = sqrtf(Xv[0]*Xv[0] + Xv[1]*Xv[1] + Xv[2]*Xv[2]);
    float ny = sqrtf(Yv[0]*Yv[0] + Yv[1]*Yv[1] + Yv[2]*Yv[2]);
    float nz = sqrtf(Zv[0]*Zv[0] + Zv[1]*Zv[1] + Zv[2]*Zv[2]);
    for (int k = 0; k < 3; k++) {
        Crow[0*3 + k] = __fdiv_rn(Xv[k], nx);
        Crow[1*3 + k] = __fdiv_rn(Yv[k], ny);
        Crow[2*3 + k] = __fdiv_rn(Zv[k], nz);
        O[k] = Zv[k];
    }
}

// cofactor numerators of M = c0^T, same expressions as the serial version
__device__ __forceinline__ double cof_num(const double M[3][3], int r, int k) {
    switch (r * 3 + k) {
        case 0: return  M[1][1]*M[2][2] - M[1][2]*M[2][1];
        case 1: return  M[0][2]*M[2][1] - M[0][1]*M[2][2];
        case 2: return  M[0][1]*M[1][2] - M[0][2]*M[1][1];
        case 3: return  M[1][2]*M[2][0] - M[1][0]*M[2][2];
        case 4: return  M[0][0]*M[2][2] - M[0][2]*M[2][0];
        case 5: return  M[0][2]*M[1][0] - M[0][0]*M[1][2];
        case 6: return  M[1][0]*M[2][1] - M[1][1]*M[2][0];
        case 7: return  M[0][1]*M[2][0] - M[0][0]*M[2][1];
        default:return  M[0][0]*M[1][1] - M[0][1]*M[1][0];
    }
}

// --- kernel A: parallel camera setup + per-point offsets --------------------
__global__ __launch_bounds__(1024)
void proj_kernel(const float* __restrict__ coord,
                 const float* __restrict__ cams, int N) {
    __shared__ CamData cam;
    int t = threadIdx.x;

    // cam_mat: thread i handles view i (independent, identical op order)
    if (t < 3) cam_mat(cams + t * 5, cam.c[t], cam.o[t]);
    __syncthreads();

    // DP inverse: thread rc = r*3+c computes inv[r][c] = cofactor/det.
    // det recomputed per thread from the same expression -> identical value
    // -> B0 bit-identical to the serial cofactor version.
    if (t < 9) {
        double M[3][3];
        for (int r = 0; r < 3; r++)
            for (int k = 0; k < 3; k++)
                M[r][k] = (double)cam.c[0][k*3 + r];   // c0^T

        double det = M[0][0]*(M[1][1]*M[2][2] - M[1][2]*M[2][1])
                   - M[0][1]*(M[1][0]*M[2][2] - M[1][2]*M[2][0])
                   + M[0][2]*(M[1][0]*M[2][1] - M[1][1]*M[2][0]);
        cam.B0[t] = (float)(cof_num(M, t / 3, t % 3) / det);
    }
    __syncthreads();

    int p = blockIdx.x * blockDim.x + t;
    if (p >= N) return;

    float x = coord[p*3 + 0];
    float y = coord[p*3 + 1];
    float z = coord[p*3 + 2];

    float po[3];
    #pragma unroll
    for (int j = 0; j < 3; j++)
        po[j] = x * cam.B0[0*3 + j] + y * cam.B0[1*3 + j]
              + z * cam.B0[2*3 + j] + cam.o[0][j];

    const int   ds[4] = { 56, 28, 14, 7 };
    const int   Cs[4] = { 64, 128, 256, 512 };
    const float qi[4] = { 0.25f, 0.125f, 0.0625f, 0.03125f };  // d/224 exact pow2

    int off[12];
    #pragma unroll
    for (int i = 0; i < 3; i++) {
        float vx = po[0] - cam.o[i][0];
        float vy = po[1] - cam.o[i][1];
        float vz = po[2] - cam.o[i][2];
        const float* C = cam.c[i];
        float X  = vx*C[0] + vy*C[1] + vz*C[2];
        float Y  = vx*C[3] + vy*C[4] + vz*C[5];
        float Zc = vx*C[6] + vy*C[7] + vz*C[8];

        float negz = -Zc;
        float h = __fdiv_rn(248.0f * (-Y), negz) + 112.0f;
        float w = __fdiv_rn(248.0f * X,    negz) + 112.0f;
        h = fminf(fmaxf(h, 0.0f), 223.0f);
        w = fminf(fmaxf(w, 0.0f), 223.0f);

        #pragma unroll
        for (int s = 0; s < 4; s++) {
            int ih = (int)(h * qi[s]);
            int iw = (int)(w * qi[s]);
            off[i*4 + s] = (ih * ds[s] + iw) * Cs[s];
        }
    }
    int4* dst = reinterpret_cast<int4*>(g_off + p*12);
    dst[0] = make_int4(off[0], off[1], off[2],  off[3]);
    dst[1] = make_int4(off[4], off[5], off[6],  off[7]);
    dst[2] = make_int4(off[8], off[9], off[10], off[11]);
}

// --- kernel B: warp-per-point rolling shifted window (R14 verbatim) ---------
__global__ __launch_bounds__(256)
void gather_kernel(const float* __restrict__ f1, const float* __restrict__ f2,
                   const float* __restrict__ f3, const float* __restrict__ f4,
                   const float* __restrict__ coord, float* __restrict__ out) {
    int wid  = threadIdx.x >> 5;
    int lane = threadIdx.x & 31;
    unsigned p = blockIdx.x * 8u + (unsigned)wid;
    unsigned g = p * (unsigned)OUT_STRIDE;              // < 2^31
    int u = (int)((32u - ((g + 3u) & 31u)) & 31u);      // g+3+u ≡ 0 (mod 32)

    int v = (lane < 12) ? g_off[p * 12u + (unsigned)lane] : 0;

    if (lane < 3) out[g + (unsigned)lane] = __ldg(coord + p * 3u + (unsigned)lane);

    int src = (lane + u) & 31;          // shuffle source for window rebuild
    bool send_prev = (lane >= u);       // lane publishes prev (else cur)

    float pm, pn, ps;                   // previous row's stats
    unsigned A;                         // running store index (window base)

    // ---- peeled row 0 (scale 0): compute stats, store head [0,u) ----
    {
        int o0 = __shfl_sync(0xFFFFFFFFu, v, 0);
        int o1 = __shfl_sync(0xFFFFFFFFu, v, 4);
        int o2 = __shfl_sync(0xFFFFFFFFu, v, 8);
        float a = __ldg(f1 + o0 + lane);
        float b = __ldg(f1 + o1 + lane);
        float d = __ldg(f1 + o2 + lane);
        pm = fmaxf(a, fmaxf(b, d));
        pn = (a + b + d) * (1.0f / 3.0f);
        float da = a - pn, db = b - pn, dc = d - pn;
        ps = sqrtf((da*da + db*db + dc*dc) * (1.0f / 3.0f));
        if (lane < u) {
            out[g + 3u + (unsigned)lane]    = pm;
            out[g + 963u + (unsigned)lane]  = pn;
            out[g + 1923u + (unsigned)lane] = ps;
        }
        A = g + 3u + (unsigned)(u + lane);
    }

    // ---- generic segment: CNT rows of scale S, local channels from CL0 ----
#define SEGMENT(F, S, CL0, CNT, UNR)                                           \
    {                                                                          \
        int o0 = __shfl_sync(0xFFFFFFFFu, v, (S));                             \
        int o1 = __shfl_sync(0xFFFFFFFFu, v, 4 + (S));                         \
        int o2 = __shfl_sync(0xFFFFFFFFu, v, 8 + (S));                         \
        int cl = (CL0) + lane;                                                 \
        _Pragma(UNR)                                                           \
        for (int kk = 0; kk < (CNT); kk++) {                                   \
            float a = __ldg((F) + o0 + cl);                                    \
            float b = __ldg((F) + o1 + cl);                                    \
            float d = __ldg((F) + o2 + cl);                                    \
            float cm = fmaxf(a, fmaxf(b, d));                                  \
            float cn = (a + b + d) * (1.0f / 3.0f);                            \
            float da = a - cn, db = b - cn, dc = d - cn;                       \
            float cs = sqrtf((da*da + db*db + dc*dc) * (1.0f / 3.0f));         \
            float wm = __shfl_sync(0xFFFFFFFFu, send_prev ? pm : cm, src);     \
            float wn = __shfl_sync(0xFFFFFFFFu, send_prev ? pn : cn, src);     \
            float ws = __shfl_sync(0xFFFFFFFFu, send_prev ? ps : cs, src);     \
            out[A]         = wm;                                               \
            out[A + 960u]  = wn;                                               \
            out[A + 1920u] = ws;                                               \
            pm = cm; pn = cn; ps = cs; cl += 32; A += 32u;                     \
        }                                                                      \
    }

    SEGMENT(f1, 0, 32,  1, "unroll")       // row 1 (scale 0 done)
    SEGMENT(f2, 1,  0,  4, "unroll 4")     // rows 2..5
    SEGMENT(f3, 2,  0,  8, "unroll 4")     // rows 6..13
    SEGMENT(f4, 3,  0, 16, "unroll 4")     // rows 14..29
#undef SEGMENT

    // ---- tail: window 29 = channels [u+928, 960), from prev only ----
    {
        float wm = __shfl_sync(0xFFFFFFFFu, pm, src);
        float wn = __shfl_sync(0xFFFFFFFFu, pn, src);
        float ws = __shfl_sync(0xFFFFFFFFu, ps, src);
        if (lane < 32 - u) {
            out[A]         = wm;
            out[A + 960u]  = wn;
            out[A + 1920u] = ws;
        }
    }
}

extern "C" void kernel_launch(void* const* d_in, const int* in_sizes, int n_in,
                              void* d_out, int out_size) {
    const float* coord = (const float*)d_in[0];
    const float* cams  = (const float*)d_in[1];
    const float* f1    = (const float*)d_in[2];
    const float* f2    = (const float*)d_in[3];
    const float* f3    = (const float*)d_in[4];
    const float* f4    = (const float*)d_in[5];
    float* out = (float*)d_out;

    int N = in_sizes[0] / 3;

    proj_kernel<<<(N + 1023) / 1024, 1024>>>(coord, cams, N);
    gather_kernel<<<N / 8, 256>>>(f1, f2, f3, f4, coord, out);
}